// round 3
// baseline (speedup 1.0000x reference)
#include <cuda_runtime.h>

// FindPeaks: 3x3 zero-padded peak detection, unfold/argmax tie-breaking:
//   peak <=> max(n0,n1,n2,n3) < c  &&  max(n5,n6,n7,n8) <= c
// out = peak ? c : 0
//
// [B,1,768,768] f32. R1 measured: L1 76.5%, ALU 65.2%, DRAM 40.2% -> bound by
// L1 wavefronts + ALU, not HBM. Fix: 16 outputs per thread (4x LDG.128 + 2
// halo scalars per row = 14 L1 accesses per 16 outputs vs 9 per 4 before),
// fmax-tree predicate to cut ALU.

static constexpr int H = 768;
static constexpr int W = 768;
static constexpr int CW = 16;           // outputs per thread
static constexpr int NCHUNK = W / CW;   // 48

__global__ __launch_bounds__(256) void find_peaks_kernel(
    const float* __restrict__ in, float* __restrict__ out, int n_img)
{
    int idx = blockIdx.x * blockDim.x + threadIdx.x;
    int total = n_img * H * NCHUNK;
    if (idx >= total) return;

    int cidx = idx % NCHUNK;
    int t    = idx / NCHUNK;
    int y    = t % H;
    int b    = t / H;
    int x0   = cidx * CW;

    const float* img = in + (size_t)b * H * W;

    const bool has_top = (y > 0);
    const bool has_bot = (y < H - 1);
    const bool has_l   = (cidx > 0);
    const bool has_r   = (cidx < NCHUNK - 1);

    // rows y-1, y, y+1: columns x0-1 .. x0+16 (18 values), zero-padded.
    float r0[CW + 2], r1[CW + 2], r2[CW + 2];

    const float* rpc = img + (size_t)y * W + x0;
    const float* rpt = rpc - W;
    const float* rpb = rpc + W;

    // Issue all wide loads first (max MLP), then halos.
    float4 vc[CW / 4], vt[CW / 4], vb[CW / 4];
    #pragma unroll
    for (int j = 0; j < CW / 4; j++)
        vc[j] = *reinterpret_cast<const float4*>(rpc + 4 * j);
    if (has_top) {
        #pragma unroll
        for (int j = 0; j < CW / 4; j++)
            vt[j] = *reinterpret_cast<const float4*>(rpt + 4 * j);
    }
    if (has_bot) {
        #pragma unroll
        for (int j = 0; j < CW / 4; j++)
            vb[j] = *reinterpret_cast<const float4*>(rpb + 4 * j);
    }

    #pragma unroll
    for (int j = 0; j < CW / 4; j++) {
        r1[1 + 4 * j] = vc[j].x; r1[2 + 4 * j] = vc[j].y;
        r1[3 + 4 * j] = vc[j].z; r1[4 + 4 * j] = vc[j].w;
    }
    r1[0]      = has_l ? rpc[-1] : 0.0f;
    r1[CW + 1] = has_r ? rpc[CW] : 0.0f;

    if (has_top) {
        #pragma unroll
        for (int j = 0; j < CW / 4; j++) {
            r0[1 + 4 * j] = vt[j].x; r0[2 + 4 * j] = vt[j].y;
            r0[3 + 4 * j] = vt[j].z; r0[4 + 4 * j] = vt[j].w;
        }
        r0[0]      = has_l ? rpt[-1] : 0.0f;
        r0[CW + 1] = has_r ? rpt[CW] : 0.0f;
    } else {
        #pragma unroll
        for (int i = 0; i < CW + 2; i++) r0[i] = 0.0f;
    }
    if (has_bot) {
        #pragma unroll
        for (int j = 0; j < CW / 4; j++) {
            r2[1 + 4 * j] = vb[j].x; r2[2 + 4 * j] = vb[j].y;
            r2[3 + 4 * j] = vb[j].z; r2[4 + 4 * j] = vb[j].w;
        }
        r2[0]      = has_l ? rpb[-1] : 0.0f;
        r2[CW + 1] = has_r ? rpb[CW] : 0.0f;
    } else {
        #pragma unroll
        for (int i = 0; i < CW + 2; i++) r2[i] = 0.0f;
    }

    float o[CW];
    #pragma unroll
    for (int i = 0; i < CW; i++) {
        float c = r1[i + 1];
        // kernel indices 0..3 strictly < c; indices 5..8 <= c
        float mstrict = fmaxf(fmaxf(r0[i], r0[i + 1]),
                              fmaxf(r0[i + 2], r1[i]));
        float mloose  = fmaxf(fmaxf(r1[i + 2], r2[i]),
                              fmaxf(r2[i + 1], r2[i + 2]));
        bool peak = (mstrict < c) & (mloose <= c);
        o[i] = peak ? c : 0.0f;
    }

    float* op = out + (size_t)b * H * W + (size_t)y * W + x0;
    #pragma unroll
    for (int j = 0; j < CW / 4; j++) {
        float4 v;
        v.x = o[4 * j]; v.y = o[4 * j + 1]; v.z = o[4 * j + 2]; v.w = o[4 * j + 3];
        *reinterpret_cast<float4*>(op + 4 * j) = v;
    }
}

extern "C" void kernel_launch(void* const* d_in, const int* in_sizes, int n_in,
                              void* d_out, int out_size)
{
    const float* in = (const float*)d_in[0];
    float* out = (float*)d_out;
    int n_img = in_sizes[0] / (H * W);   // C==1
    int total = n_img * H * NCHUNK;
    int block = 256;
    int grid = (total + block - 1) / block;
    find_peaks_kernel<<<grid, block>>>(in, out, n_img);
}

// round 5
// speedup vs baseline: 2.0508x; 2.0508x over previous
#include <cuda_runtime.h>

// FindPeaks: 3x3 zero-padded peak detection, unfold/argmax tie-breaking:
//   peak <=> max(strict nbrs: idx 0..3) < c  &&  max(loose nbrs: idx 5..8) <= c
// out = peak ? c : 0.   [B,1,768,768] f32.
//
// R1: 1 float4/thread -> L1 76.5% (bound), 34.5us.
// R3: 16 contiguous floats/thread -> broke coalescing (lanes 64B apart), 58us.
// Now: 4 rows x 4 floats per thread, lane-adjacent float4 (perfect coalescing),
//      halos via __shfl (no strided scalar loads except warp edges).

static constexpr int H = 768;
static constexpr int W = 768;
static constexpr int RPT = 4;                 // output rows per thread
static constexpr int SPAN = 128;              // floats per warp in x
static constexpr int XS = W / SPAN;           // 6 warp spans per row
static constexpr int YG = H / RPT;            // 192 row groups

__global__ __launch_bounds__(256) void find_peaks_kernel(
    const float* __restrict__ in, float* __restrict__ out, int n_img)
{
    int wg   = (blockIdx.x * blockDim.x + threadIdx.x) >> 5;  // global warp id
    int lane = threadIdx.x & 31;
    int total_warps = n_img * YG * XS;
    if (wg >= total_warps) return;

    int xs = wg % XS;
    int t  = wg / XS;
    int yg = t % YG;
    int b  = t / YG;
    int y0 = yg * RPT;
    int x  = xs * SPAN + lane * 4;

    const float* img = in + (size_t)b * H * W;

    const bool has_l = (xs > 0);
    const bool has_r = (xs < XS - 1);

    // 6 rows: y0-1 .. y0+4; each = lane float4 + left/right halo via shfl.
    float4 v[RPT + 2];
    float  lh[RPT + 2], rh[RPT + 2];

    // Wide loads first (max MLP). y-range conditions are warp-uniform.
    #pragma unroll
    for (int k = 0; k < RPT + 2; k++) {
        int y = y0 + k - 1;
        if (y >= 0 && y < H)
            v[k] = *reinterpret_cast<const float4*>(img + (size_t)y * W + x);
        else
            v[k] = make_float4(0.f, 0.f, 0.f, 0.f);
    }

    // Halos: interior lanes from shuffles; warp-edge lanes from scalar loads.
    #pragma unroll
    for (int k = 0; k < RPT + 2; k++) {
        int y = y0 + k - 1;
        float lu = __shfl_up_sync(0xFFFFFFFFu,  v[k].w, 1);
        float rd = __shfl_down_sync(0xFFFFFFFFu, v[k].x, 1);
        bool in_y = (y >= 0 && y < H);
        float le = 0.0f, re = 0.0f;
        if (in_y) {
            const float* rp = img + (size_t)y * W;
            if (lane == 0  && has_l) le = rp[x - 1];
            if (lane == 31 && has_r) re = rp[x + 4];
        }
        lh[k] = (lane == 0)  ? le : lu;
        rh[k] = (lane == 31) ? re : rd;
    }

    float* obase = out + (size_t)b * H * W + x;

    #pragma unroll
    for (int k = 0; k < RPT; k++) {
        float tw[6] = { lh[k],     v[k].x,   v[k].y,   v[k].z,   v[k].w,   rh[k]     };
        float mw[6] = { lh[k + 1], v[k+1].x, v[k+1].y, v[k+1].z, v[k+1].w, rh[k + 1] };
        float bw[6] = { lh[k + 2], v[k+2].x, v[k+2].y, v[k+2].z, v[k+2].w, rh[k + 2] };

        float4 o;
        float* op = &o.x;
        #pragma unroll
        for (int i = 0; i < 4; i++) {
            float c = mw[i + 1];
            // kernel idx 0..3 strictly < c; idx 5..8 <= c
            float ms = fmaxf(fmaxf(tw[i], tw[i + 1]), fmaxf(tw[i + 2], mw[i]));
            float ml = fmaxf(fmaxf(mw[i + 2], bw[i]), fmaxf(bw[i + 1], bw[i + 2]));
            op[i] = ((ms < c) & (ml <= c)) ? c : 0.0f;
        }
        *reinterpret_cast<float4*>(obase + (size_t)(y0 + k) * W) = o;
    }
}

extern "C" void kernel_launch(void* const* d_in, const int* in_sizes, int n_in,
                              void* d_out, int out_size)
{
    const float* in = (const float*)d_in[0];
    float* out = (float*)d_out;
    int n_img = in_sizes[0] / (H * W);            // C==1
    int total_warps = n_img * YG * XS;            // 36864 for B=32
    int total_threads = total_warps * 32;
    int block = 256;
    int grid = (total_threads + block - 1) / block;
    find_peaks_kernel<<<grid, block>>>(in, out, n_img);
}